// round 14
// baseline (speedup 1.0000x reference)
#include <cuda_runtime.h>
#include <cstdint>

// NMS_5549097746496: fused 8x8x8 MaxPool -> MaxUnpool -> threshold(0.5) -> (thresholded == x)
// Input:  raw [2,3,128,256,256] fp32 ; Output: mask as float32 0/1.
//
// out[i] = (x[i]==0) ? 1 : 0 everywhere, EXCEPT the block-argmax position when
// bmax > 0.5, which is 1 (the unpooled value there is bit-identical to x).
// Phase 1 streams (x==0); phase 2 overwrites one element per hot window
// (same-thread program order -> correctly ordered).
//
// R14 change: tail-granularity experiment. Warp-level structure is IDENTICAL to
// the verified best (R10/R13: burst-16 LDG.128 staging, warp owns a 64-float
// span, lane = win|dzh|wc, 2 planes x 256B contiguous per load instruction,
// L1~43%). Only the CTA shrinks: 64 threads (2 warps), tile 8d x 8h x 128w,
// grid 6144, 12 CTAs/SM (same 24 warps/SM). Halves T_tile so the ragged
// final wave packs ~2x better. If neutral/regressed, R13 config is final.

#define NMS_THRESH 0.5f

__global__ __launch_bounds__(64, 12)
void nms_mask_kernel(const float* __restrict__ in, float* __restrict__ out) {
    const int W = 256;
    const int HW = 256 * 256;

    int bid  = blockIdx.x;        // 6 * 16 * 32 * 2 = 6144
    int wseg = bid & 1;           // which 128-float half of the w row
    int hblk = (bid >> 1) & 31;   // 32 h-windows
    int dblk = (bid >> 6) & 15;   // 16 d-windows
    int bc   = bid >> 10;         // 6

    int lane = threadIdx.x & 31;
    int warp = threadIdx.x >> 5;  // 0..1, 64-float w-span within the 128-float segment
    int win  = lane >> 2;         // 0..7  window within warp span
    int dzh  = (lane >> 1) & 1;   // 0..1  dz half (dz = dzh*4 + dzl)
    int wc   = lane & 1;          // 0..1  16B chunk within window row

    // window-origin offset (dz=0,dy=0,dx=0) for this lane's window
    size_t wbase = ((size_t)(bc * 128 + dblk * 8)) * HW
                 + (size_t)(hblk * 8) * W
                 + (size_t)(wseg * 128 + warp * 64 + win * 8);
    // this lane's chunk base
    size_t mybase = wbase + (size_t)dzh * 4 * HW + (size_t)wc * 4;

    const float* p = in  + mybase;
    float*       q = out + mybase;

    float best  = __int_as_float(0xff800000);  // -inf
    int   bestE = 1 << 30;

    #pragma unroll
    for (int half = 0; half < 2; half++) {
        const int dz0 = half * 2;   // planes dz0, dz0+1 of this dz-half

        // ---- stage two dz-planes: 16 independent LDG.128 (MLP=16) ----
        float4 v[2][8];
        #pragma unroll
        for (int pl = 0; pl < 2; pl++)
            #pragma unroll
            for (int dy = 0; dy < 8; dy++)
                v[pl][dy] = __ldcs(reinterpret_cast<const float4*>(
                                p + (dz0 + pl) * HW + dy * W));

        // ---- emit mask + update running (max, argE) ----
        #pragma unroll
        for (int pl = 0; pl < 2; pl++) {
            #pragma unroll
            for (int dy = 0; dy < 8; dy++) {
                float4 x = v[pl][dy];
                float4 m;
                m.x = (x.x == 0.0f) ? 1.0f : 0.0f;
                m.y = (x.y == 0.0f) ? 1.0f : 0.0f;
                m.z = (x.z == 0.0f) ? 1.0f : 0.0f;
                m.w = (x.w == 0.0f) ? 1.0f : 0.0f;
                __stcs(reinterpret_cast<float4*>(q + (dz0 + pl) * HW + dy * W), m);

                int eb = (dzh * 4 + dz0 + pl) * 64 + dy * 8 + wc * 4;  // K-index of x.x
                // full lexicographic comparator (value desc, e asc) -> order-independent
                if (x.x > best || (x.x == best && eb + 0 < bestE)) { best = x.x; bestE = eb + 0; }
                if (x.y > best || (x.y == best && eb + 1 < bestE)) { best = x.y; bestE = eb + 1; }
                if (x.z > best || (x.z == best && eb + 2 < bestE)) { best = x.z; bestE = eb + 2; }
                if (x.w > best || (x.w == best && eb + 3 < bestE)) { best = x.w; bestE = eb + 3; }
            }
        }
    }

    // remember local candidate to identify the owning lane afterwards
    float lbest = best; int lE = bestE;

    // reduce across the 4 lanes of this window (xor 1,2 stays in aligned group of 4)
    #pragma unroll
    for (int msk = 1; msk < 4; msk <<= 1) {
        float ov = __shfl_xor_sync(0xffffffffu, best,  msk);
        int   oe = __shfl_xor_sync(0xffffffffu, bestE, msk);
        if (ov > best || (ov == best && oe < bestE)) { best = ov; bestE = oe; }
    }

    // phase 2: the lane that loaded the winning element rewrites it to 1.0 if hot.
    // K-index e is unique across the window, so exactly one lane matches.
    if (best > NMS_THRESH && lbest == best && lE == bestE) {
        int dz = bestE >> 6, dy = (bestE >> 3) & 7, dx = bestE & 7;
        out[wbase + (size_t)dz * HW + (size_t)dy * W + dx] = 1.0f;
    }
}

extern "C" void kernel_launch(void* const* d_in, const int* in_sizes, int n_in,
                              void* d_out, int out_size) {
    (void)in_sizes; (void)n_in; (void)out_size;
    const float* in = (const float*)d_in[0];
    float* out = (float*)d_out;
    // bc(6) * dblk(16) * hblk(32) * wseg(2) = 6144 CTAs, 64 threads each
    nms_mask_kernel<<<6144, 64>>>(in, out);
}

// round 16
// speedup vs baseline: 1.0032x; 1.0032x over previous
#include <cuda_runtime.h>
#include <cstdint>

// NMS_5549097746496: fused 8x8x8 MaxPool -> MaxUnpool -> threshold(0.5) -> (thresholded == x)
// Input:  raw [2,3,128,256,256] fp32 ; Output: mask as float32 0/1.
//
// out[i] = (x[i]==0) ? 1 : 0 everywhere, EXCEPT the block-argmax position when
// bmax > 0.5, which is 1 (the unpooled value there is bit-identical to x).
// Phase 1 streams (x==0); phase 2 overwrites one element per hot window.
//
// R16: fixes R15's bug -- window K-index e ranges 0..511 (8x8x8), so the packed
// key's low field must be (511 - e), 9 bits, not (63 - e). u64 max over
// key = (orderable(f) << 32) | (511 - e)  ==  lexicographic (value desc, e asc),
// exactly the reference's first-occurrence argmax. Short ALU max tree replaces
// the 64-link predicated compare-select chain.
// Config = R14 (best kernel time 60.2us): 64-thr CTAs, tile 8d x 8h x 128w,
// grid 6144, burst-16 LDG.128 staging, proven warp mapping (L1~43%).

#define NMS_HOT_KEY 0xBF000000u   // orderable(0.5f); bits(0.5f)=0x3F000000 | signflip

__device__ __forceinline__ unsigned ordkey(float f) {
    unsigned b = __float_as_uint(f);
    // negatives: ~b ; non-negatives: b | 0x80000000  (monotone in f)
    unsigned m = (unsigned)((int)b >> 31);
    return b ^ (m | 0x80000000u);
}

__global__ __launch_bounds__(64, 12)
void nms_mask_kernel(const float* __restrict__ in, float* __restrict__ out) {
    const int W = 256;
    const int HW = 256 * 256;

    int bid  = blockIdx.x;        // 6 * 16 * 32 * 2 = 6144
    int wseg = bid & 1;           // which 128-float half of the w row
    int hblk = (bid >> 1) & 31;   // 32 h-windows
    int dblk = (bid >> 6) & 15;   // 16 d-windows
    int bc   = bid >> 10;         // 6

    int lane = threadIdx.x & 31;
    int warp = threadIdx.x >> 5;  // 0..1, 64-float w-span within the segment
    int win  = lane >> 2;         // 0..7  window within warp span
    int dzh  = (lane >> 1) & 1;   // 0..1  dz half (dz = dzh*4 + dzl)
    int wc   = lane & 1;          // 0..1  16B chunk within window row

    // window-origin offset (dz=0,dy=0,dx=0) for this lane's window
    size_t wbase = ((size_t)(bc * 128 + dblk * 8)) * HW
                 + (size_t)(hblk * 8) * W
                 + (size_t)(wseg * 128 + warp * 64 + win * 8);
    // this lane's chunk base
    size_t mybase = wbase + (size_t)dzh * 4 * HW + (size_t)wc * 4;

    const float* p = in  + mybase;
    float*       q = out + mybase;

    unsigned long long bestK = 0ull;

    #pragma unroll
    for (int half = 0; half < 2; half++) {
        const int dz0 = half * 2;   // planes dz0, dz0+1 of this dz-half

        // ---- stage two dz-planes: 16 independent LDG.128 (MLP=16) ----
        float4 v[2][8];
        #pragma unroll
        for (int pl = 0; pl < 2; pl++)
            #pragma unroll
            for (int dy = 0; dy < 8; dy++)
                v[pl][dy] = __ldcs(reinterpret_cast<const float4*>(
                                p + (dz0 + pl) * HW + dy * W));

        // ---- emit mask + packed-key argmax (short ALU tree, no pred chain) ----
        #pragma unroll
        for (int pl = 0; pl < 2; pl++) {
            #pragma unroll
            for (int dy = 0; dy < 8; dy++) {
                float4 x = v[pl][dy];
                float4 m;
                m.x = (x.x == 0.0f) ? 1.0f : 0.0f;
                m.y = (x.y == 0.0f) ? 1.0f : 0.0f;
                m.z = (x.z == 0.0f) ? 1.0f : 0.0f;
                m.w = (x.w == 0.0f) ? 1.0f : 0.0f;
                __stcs(reinterpret_cast<float4*>(q + (dz0 + pl) * HW + dy * W), m);

                int eb = (dzh * 4 + dz0 + pl) * 64 + dy * 8 + wc * 4;  // K-index of x.x, 0..511
                // key64 = (ordkey << 32) | (511 - e): u64 max == (value desc, e asc)
                unsigned long long k0 = ((unsigned long long)ordkey(x.x) << 32) | (unsigned)(511 - (eb + 0));
                unsigned long long k1 = ((unsigned long long)ordkey(x.y) << 32) | (unsigned)(511 - (eb + 1));
                unsigned long long k2 = ((unsigned long long)ordkey(x.z) << 32) | (unsigned)(511 - (eb + 2));
                unsigned long long k3 = ((unsigned long long)ordkey(x.w) << 32) | (unsigned)(511 - (eb + 3));
                unsigned long long ka = k0 > k1 ? k0 : k1;
                unsigned long long kb = k2 > k3 ? k2 : k3;
                unsigned long long kc = ka > kb ? ka : kb;
                bestK = kc > bestK ? kc : bestK;
            }
        }
    }

    // remember local candidate to identify the owning lane afterwards
    unsigned long long lK = bestK;

    // reduce across the 4 lanes of this window (xor 1,2 stays in aligned group of 4)
    #pragma unroll
    for (int msk = 1; msk < 4; msk <<= 1) {
        unsigned long long ok = __shfl_xor_sync(0xffffffffu, bestK, msk);
        bestK = ok > bestK ? ok : bestK;
    }

    // phase 2: the lane that loaded the winning element rewrites it to 1.0 if hot.
    // key64 is unique across the window (e unique), so exactly one lane matches.
    unsigned bestKey32 = (unsigned)(bestK >> 32);
    if (bestKey32 > NMS_HOT_KEY && lK == bestK) {
        int e  = 511 - (int)(bestK & 511u);
        int dz = e >> 6, dy = (e >> 3) & 7, dx = e & 7;
        out[wbase + (size_t)dz * HW + (size_t)dy * W + dx] = 1.0f;
    }
}

extern "C" void kernel_launch(void* const* d_in, const int* in_sizes, int n_in,
                              void* d_out, int out_size) {
    (void)in_sizes; (void)n_in; (void)out_size;
    const float* in = (const float*)d_in[0];
    float* out = (float*)d_out;
    // bc(6) * dblk(16) * hblk(32) * wseg(2) = 6144 CTAs, 64 threads each
    nms_mask_kernel<<<6144, 64>>>(in, out);
}